// round 4
// baseline (speedup 1.0000x reference)
#include <cuda_runtime.h>

// RegionPartitioner: x (8,4,500,500) f32, region=64, step=32, edge pad to 512.
// out (8, 225, 4, 64, 64): out[b,r,c,i,j] = x[b,c,min(ri*32+i,499),min(rj*32+j,499)],
// r = ri*15 + rj, ri/rj in 0..14.
//
// Input-centric, each input element loaded exactly once chip-wide.
// Block = 64-row x 32-col band = two stacked 32x32 quadrant tiles (tiA=2*band,
// tiB=2*band+1). 256 threads, each loads 2 float4 (MLP=2, front-batched),
// then scatters to up to 4 regions per tile (block-uniform branches).

namespace {
constexpr int C  = 4;
constexpr int H  = 500;
constexpr int W  = 500;
constexpr int NR = 15;
constexpr int R  = NR * NR;   // 225
}

__global__ void __launch_bounds__(256)
region_partition_kernel(const float* __restrict__ x, float4* __restrict__ out) {
    const int band = blockIdx.x >> 4;      // 0..7  (64-row band)
    const int tj   = blockIdx.x & 15;      // 0..15 (32-col tile)
    const int c    = blockIdx.y;
    const int b    = blockIdx.z;

    const int t    = threadIdx.x;
    const int rowl = t >> 3;               // 0..31 row within quadrant tile
    const int col4 = t & 7;                // 0..7  float4 col within tile

    const int tiA = band << 1;             // upper quadrant tile row idx
    const int tiB = tiA + 1;               // lower

    // ---- two independent loads, front-batched (edge clamp) ----
    int rowA = tiA * 32 + rowl;  if (rowA >= H) rowA = H - 1;
    int rowB = rowA + 32;        if (rowB >= H) rowB = H - 1;
    const int col0 = tj * 32 + (col4 << 2);
    const float* __restrict__ plane = x + ((b * C + c) * H) * (long)W;

    float4 v0, v1;
    if (col0 + 3 < W) {
        v0 = *reinterpret_cast<const float4*>(plane + rowA * W + col0);
        v1 = *reinterpret_cast<const float4*>(plane + rowB * W + col0);
    } else {                                // tj==15 edge only
        const int c0 = col0     < W ? col0     : W - 1;
        const int c1 = col0 + 1 < W ? col0 + 1 : W - 1;
        const int c2 = col0 + 2 < W ? col0 + 2 : W - 1;
        const int c3 = col0 + 3 < W ? col0 + 3 : W - 1;
        const float* sA = plane + rowA * W;
        const float* sB = plane + rowB * W;
        v0.x = sA[c0]; v0.y = sA[c1]; v0.z = sA[c2]; v0.w = sA[c3];
        v1.x = sB[c0]; v1.y = sB[c1]; v1.z = sB[c2]; v1.w = sB[c3];
    }

    // ---- scatter: tile ti -> regions ri in {ti-1, ti} ∩ [0,14], quadrant qi = ti-ri
    const int breg   = b * R;
    const int colOff = (col4);             // within-row float4 index (plus qj*8)

    #pragma unroll
    for (int half = 0; half < 2; half++) {
        const int   ti = half ? tiB : tiA;
        const float4 v = half ? v1  : v0;
        #pragma unroll
        for (int di = 0; di < 2; di++) {
            const int ri = ti - 1 + di;
            if (ri < 0 || ri > NR - 1) continue;
            const int qi   = 1 - di;
            const int orow = (qi << 5) + rowl;           // 0..63
            #pragma unroll
            for (int dj = 0; dj < 2; dj++) {
                const int rj = tj - 1 + dj;
                if (rj < 0 || rj > NR - 1) continue;
                const int qj = 1 - dj;
                const long base4 = (((long)(breg + ri * NR + rj) * C + c) << 10);
                out[base4 + orow * 16 + (qj << 3) + colOff] = v;
            }
        }
    }
}

extern "C" void kernel_launch(void* const* d_in, const int* in_sizes, int n_in,
                              void* d_out, int out_size) {
    const float* x = (const float*)d_in[0];
    float4* out = (float4*)d_out;
    dim3 grid(128, C, 8);                  // (8 bands * 16 tj, c, b) = 4096 blocks
    region_partition_kernel<<<grid, 256>>>(x, out);
}

// round 5
// speedup vs baseline: 1.0491x; 1.0491x over previous
#include <cuda_runtime.h>

// RegionPartitioner: x (8,4,500,500) f32, region=64, step=32, edge pad to 512.
// out (8, 225, 4, 64, 64): out[b,r,c,i,j] = x[b,c,min(ri*32+i,499),min(rj*32+j,499)],
// r = ri*15 + rj, ri/rj in 0..14.
//
// Input-centric (each input element loaded exactly once chip-wide), one block
// per 32x32 quadrant tile, scatter to up to 4 regions. R5 delta: streaming
// cache hints — __ldcs on the read-once input, __stcs on the write-once output
// so 118MB of dead store lines don't thrash L2 / mix with reads.

namespace {
constexpr int C  = 4;
constexpr int H  = 500;
constexpr int W  = 500;
constexpr int NR = 15;
constexpr int R  = NR * NR;   // 225
}

__global__ void __launch_bounds__(256)
region_partition_kernel(const float* __restrict__ x, float4* __restrict__ out) {
    const int tile = blockIdx.x;       // 0..255
    const int ti   = tile >> 4;        // 0..15
    const int tj   = tile & 15;        // 0..15
    const int c    = blockIdx.y;
    const int b    = blockIdx.z;

    const int t    = threadIdx.x;
    const int rowl = t >> 3;           // 0..31 row within tile
    const int col4 = t & 7;            // 0..7  float4 col within tile

    // ---- load exactly once chip-wide (streaming), with edge clamp ----
    int row = ti * 32 + rowl;
    if (row >= H) row = H - 1;
    const int col0 = tj * 32 + (col4 << 2);
    const float* __restrict__ src = x + ((b * C + c) * H + row) * (long)W;

    float4 v;
    if (col0 + 3 < W) {
        v = __ldcs(reinterpret_cast<const float4*>(src + col0));   // 16B aligned
    } else {                                                       // tj==15 edge
        const int c0 = col0     < W ? col0     : W - 1;
        const int c1 = col0 + 1 < W ? col0 + 1 : W - 1;
        const int c2 = col0 + 2 < W ? col0 + 2 : W - 1;
        const int c3 = col0 + 3 < W ? col0 + 3 : W - 1;
        v.x = src[c0]; v.y = src[c1]; v.z = src[c2]; v.w = src[c3];
    }

    // ---- streaming stores to up to 4 destination regions ----
    const int breg = b * R;
    #pragma unroll
    for (int di = 0; di < 2; di++) {
        const int ri = ti - 1 + di;
        if (ri < 0 || ri > NR - 1) continue;
        const int qi   = 1 - di;
        const int orow = (qi << 5) + rowl;               // 0..63
        #pragma unroll
        for (int dj = 0; dj < 2; dj++) {
            const int rj = tj - 1 + dj;
            if (rj < 0 || rj > NR - 1) continue;
            const int qj = 1 - dj;
            const long base4 = (((long)(breg + ri * NR + rj) * C + c) << 10);
            __stcs(out + base4 + orow * 16 + (qj << 3) + col4, v);
        }
    }
}

extern "C" void kernel_launch(void* const* d_in, const int* in_sizes, int n_in,
                              void* d_out, int out_size) {
    const float* x = (const float*)d_in[0];
    float4* out = (float4*)d_out;
    dim3 grid(256, C, 8);              // (tiles, c, b) = 8192 blocks
    region_partition_kernel<<<grid, 256>>>(x, out);
}

// round 7
// speedup vs baseline: 1.1664x; 1.1118x over previous
#include <cuda_runtime.h>
#include <cstdint>

// RegionPartitioner: x (8,4,500,500) f32, region=64, step=32, edge pad to 512.
// out (8, 225, 4, 64, 64): out[b,r,c,i,j] = x[b,c,min(ri*32+i,499),min(rj*32+j,499)],
// r = ri*15 + rj, ri/rj in 0..14.
//
// Input-centric (each input element loaded exactly once chip-wide), one block
// per 32x32 quadrant tile, scatter to up to 4 regions.
// R7 delta: input loads pinned in L2 via createpolicy.fractional.L2::evict_last
// + ld.global.nc.L2::cache_hint (the 16B-encodable form; direct .L2::evict_last
// modifier requires 32B vectors on sm_103). Output stores streaming (st.cs).

namespace {
constexpr int C  = 4;
constexpr int H  = 500;
constexpr int W  = 500;
constexpr int NR = 15;
constexpr int R  = NR * NR;   // 225
}

__device__ __forceinline__ float4 ldg_pin_v4(const float4* p, uint64_t pol) {
    float4 v;
    asm volatile("ld.global.nc.L2::cache_hint.v4.f32 {%0,%1,%2,%3}, [%4], %5;"
                 : "=f"(v.x), "=f"(v.y), "=f"(v.z), "=f"(v.w)
                 : "l"(p), "l"(pol));
    return v;
}

__global__ void __launch_bounds__(256)
region_partition_kernel(const float* __restrict__ x, float4* __restrict__ out) {
    const int tile = blockIdx.x;       // 0..255
    const int ti   = tile >> 4;        // 0..15
    const int tj   = tile & 15;        // 0..15
    const int c    = blockIdx.y;
    const int b    = blockIdx.z;

    const int t    = threadIdx.x;
    const int rowl = t >> 3;           // 0..31 row within tile
    const int col4 = t & 7;            // 0..7  float4 col within tile

    uint64_t pol;
    asm("createpolicy.fractional.L2::evict_last.b64 %0, 1.0;" : "=l"(pol));

    // ---- load exactly once chip-wide, L2-pinned, with edge clamp ----
    int row = ti * 32 + rowl;
    if (row >= H) row = H - 1;
    const int col0 = tj * 32 + (col4 << 2);
    const float* __restrict__ src = x + ((b * C + c) * H + row) * (long)W;

    float4 v;
    if (col0 + 3 < W) {
        v = ldg_pin_v4(reinterpret_cast<const float4*>(src + col0), pol);
    } else {                                                       // tj==15 edge
        const int c0 = col0     < W ? col0     : W - 1;
        const int c1 = col0 + 1 < W ? col0 + 1 : W - 1;
        const int c2 = col0 + 2 < W ? col0 + 2 : W - 1;
        const int c3 = col0 + 3 < W ? col0 + 3 : W - 1;
        v.x = src[c0]; v.y = src[c1]; v.z = src[c2]; v.w = src[c3];
    }

    // ---- streaming stores to up to 4 destination regions ----
    const int breg = b * R;
    #pragma unroll
    for (int di = 0; di < 2; di++) {
        const int ri = ti - 1 + di;
        if (ri < 0 || ri > NR - 1) continue;
        const int qi   = 1 - di;
        const int orow = (qi << 5) + rowl;               // 0..63
        #pragma unroll
        for (int dj = 0; dj < 2; dj++) {
            const int rj = tj - 1 + dj;
            if (rj < 0 || rj > NR - 1) continue;
            const int qj = 1 - dj;
            const long base4 = (((long)(breg + ri * NR + rj) * C + c) << 10);
            __stcs(out + base4 + orow * 16 + (qj << 3) + col4, v);
        }
    }
}

extern "C" void kernel_launch(void* const* d_in, const int* in_sizes, int n_in,
                              void* d_out, int out_size) {
    const float* x = (const float*)d_in[0];
    float4* out = (float4*)d_out;
    dim3 grid(256, C, 8);              // (tiles, c, b) = 8192 blocks
    region_partition_kernel<<<grid, 256>>>(x, out);
}